// round 9
// baseline (speedup 1.0000x reference)
#include <cuda_runtime.h>
#include <cuda_bf16.h>
#include <cstdint>

#define BINS 256
#define NCOP 8              // one smem histogram copy per warp
#define TILE_V4 1024        // float4 per tile = 16 KB
#define STAGES 2
#define GRID 512            // 16384 tiles / 512 = exactly 32 tiles per block
#define THREADS 256

// Scratch (device globals). Zero-initialized at load; last block resets each
// launch so every graph replay starts clean.
__device__ unsigned int g_hist[BINS];
__device__ unsigned int g_ticket;

__device__ __forceinline__ uint32_t smem_u32(const void* p) {
    return (uint32_t)__cvta_generic_to_shared(p);
}
__device__ __forceinline__ void mbar_init(uint32_t a, uint32_t cnt) {
    asm volatile("mbarrier.init.shared.b64 [%0], %1;" :: "r"(a), "r"(cnt) : "memory");
}
__device__ __forceinline__ void mbar_expect_tx(uint32_t a, uint32_t bytes) {
    asm volatile("mbarrier.arrive.expect_tx.shared.b64 _, [%0], %1;"
                 :: "r"(a), "r"(bytes) : "memory");
}
__device__ __forceinline__ void mbar_arrive(uint32_t a) {
    asm volatile("mbarrier.arrive.shared.b64 _, [%0];" :: "r"(a) : "memory");
}
__device__ __forceinline__ void mbar_wait(uint32_t a, uint32_t parity) {
    asm volatile(
        "{\n\t.reg .pred P;\n\t"
        "W_%=:\n\t"
        "mbarrier.try_wait.parity.acquire.cta.shared::cta.b64 P, [%0], %1, 0x989680;\n\t"
        "@P bra.uni D_%=;\n\t"
        "bra.uni W_%=;\n\t"
        "D_%=:\n\t}"
        :: "r"(a), "r"(parity) : "memory");
}
__device__ __forceinline__ void bulk_ld(uint32_t dst, const void* src,
                                        uint32_t bytes, uint32_t mbar) {
    asm volatile(
        "cp.async.bulk.shared::cta.global.mbarrier::complete_tx::bytes [%0], [%1], %2, [%3];"
        :: "r"(dst), "l"(src), "r"(bytes), "r"(mbar) : "memory");
}

__device__ __forceinline__ void bin_one(float x, unsigned int* hist) {
    // torch.histc over [-4,4]: x==4 -> last bin; outside/NaN ignored.
    // |x|<=4 is one FSETP; fmaf(x,32,128)==round((x+4)*32) bit-exact.
    if (fabsf(x) <= 4.0f) {
        float t = fmaf(x, 32.0f, 128.0f);
        int idx = __float2int_rd(t);
        idx = min(idx, BINS - 1);
        atomicAdd(&hist[idx], 1u);
    }
}
__device__ __forceinline__ void bin4(float4 v, unsigned int* h) {
    bin_one(v.x, h); bin_one(v.y, h); bin_one(v.z, h); bin_one(v.w, h);
}

__global__ void __launch_bounds__(THREADS)
hist_kernel(const float* __restrict__ x, long long n,
            float* __restrict__ out, int out_size) {
    __shared__ float4 tiles[STAGES][TILE_V4];                 // 32 KB
    __shared__ unsigned int sh[NCOP][BINS];                   // 8 KB
    __shared__ unsigned long long mbar[2 * STAGES];           // full[s], empty[s]
    __shared__ bool is_last;

    const int tid  = threadIdx.x;
    const int warp = tid >> 5;
    unsigned int* wh = sh[warp];

    const uint32_t mb = smem_u32(mbar);
    const uint32_t full0  = mb;                  // full[s]  = mb + 8*s
    const uint32_t empty0 = mb + 8 * STAGES;     // empty[s] = mb + 8*(STAGES+s)

    if (tid == 0) {
        #pragma unroll
        for (int s = 0; s < STAGES; s++) {
            mbar_init(full0 + 8 * s, 1);
            mbar_init(empty0 + 8 * s, THREADS);
        }
    }
    #pragma unroll
    for (int i = tid; i < NCOP * BINS; i += THREADS)
        ((unsigned int*)sh)[i] = 0u;
    __syncthreads();

    const long long n4 = n >> 2;
    const float4* __restrict__ x4 = (const float4*)x;
    const long long GD = gridDim.x;
    const long long NT = (n4 + TILE_V4 - 1) / TILE_V4;

    // Producer prologue: fill both stages (stages known-empty; no wait needed).
    if (tid == 0) {
        #pragma unroll
        for (int s = 0; s < STAGES; s++) {
            long long t = (long long)blockIdx.x + (long long)s * GD;
            if (t < NT) {
                long long base = t * TILE_V4;
                uint32_t bytes = (uint32_t)(min((long long)TILE_V4, n4 - base) * 16);
                mbar_expect_tx(full0 + 8 * s, bytes);
                bulk_ld(smem_u32(tiles[s]), x4 + base, bytes, full0 + 8 * s);
            }
        }
    }

    // Main loop. Tile jj (local index) uses stage jj%2, flip-parity (jj/2)&1
    // on BOTH its full barrier (TMA completion #jj/2 of that stage) and its
    // empty barrier (consumer completion #jj/2 of that stage).
    int jj = 0;
    for (long long t = blockIdx.x; t < NT; t += GD, jj++) {
        const int s = jj & 1;
        const uint32_t ph = (uint32_t)((jj >> 1) & 1);
        const uint32_t fb = full0 + 8 * s;
        const uint32_t eb = empty0 + 8 * s;

        mbar_wait(fb, ph);                       // acquire: tile data visible

        long long base = t * TILE_V4;
        int cnt = (int)min((long long)TILE_V4, n4 - base);
        const float4* ts = tiles[s];
        if (cnt == TILE_V4) {
            float4 a = ts[tid];
            float4 b = ts[tid + 256];
            float4 c = ts[tid + 512];
            float4 d = ts[tid + 768];
            bin4(a, wh); bin4(b, wh); bin4(c, wh); bin4(d, wh);
        } else {
            for (int k = tid; k < cnt; k += THREADS)
                bin4(ts[k], wh);
        }
        mbar_arrive(eb);

        // Producer: refill this stage with tile t + STAGES*GD.
        long long tn = t + (long long)STAGES * GD;
        if (tid == 0 && tn < NT) {
            mbar_wait(eb, ph);                   // all 256 consumers done
            long long nb = tn * TILE_V4;
            uint32_t bytes = (uint32_t)(min((long long)TILE_V4, n4 - nb) * 16);
            mbar_expect_tx(fb, bytes);
            bulk_ld(smem_u32(tiles[s]), x4 + nb, bytes, fb);
        }
    }

    // Scalar tail (n not multiple of 4) — block 0 reads gmem directly.
    if (blockIdx.x == 0) {
        for (long long j = (n4 << 2) + tid; j < n; j += THREADS)
            bin_one(x[j], wh);
    }
    __syncthreads();

    // Reduce the copies, one gmem atomic per bin per block.
    for (int b = tid; b < BINS; b += THREADS) {
        unsigned int sum = 0;
        #pragma unroll
        for (int c = 0; c < NCOP; c++) sum += sh[c][b];
        if (sum) atomicAdd(&g_hist[b], sum);
    }

    // Last-block finalize: write output, reset globals for next replay.
    __threadfence();
    __syncthreads();
    if (tid == 0)
        is_last = (atomicAdd(&g_ticket, 1u) == (unsigned)gridDim.x - 1u);
    __syncthreads();

    if (is_last) {
        __threadfence();
        unsigned int v = g_hist[tid];
        g_hist[tid] = 0u;
        if (tid == 0) g_ticket = 0u;
        float fv = (float)v;
        for (int base = 0; base + tid < out_size; base += BINS)
            out[base + tid] = fv;   // reference returns (h, h)
    }
}

extern "C" void kernel_launch(void* const* d_in, const int* in_sizes, int n_in,
                              void* d_out, int out_size) {
    const float* x = (const float*)d_in[0];
    long long n = (long long)in_sizes[0];
    float* out = (float*)d_out;

    hist_kernel<<<GRID, THREADS>>>(x, n, out, out_size);
}